// round 10
// baseline (speedup 1.0000x reference)
#include <cuda_runtime.h>
#include <cstdint>

constexpr int   B = 8, F = 16, K = 24;
constexpr int   L = 384 * 384;          // 147456 pixels per (b, plane)
constexpr float EPSV       = 1e-8f;
constexpr float DELTA_VAR  = 0.5f;
constexpr float DELTA_DIST = 1.5f;
constexpr float GAMMA      = 0.001f;

// Scratch (device globals; statically zero-initialized for the first call,
// re-zeroed by the last k_var block for subsequent graph replays)
__device__ float g_sums[B * F * K];
__device__ float g_tsum[B * K];
__device__ float g_means[B * F * K];
__device__ float g_m2[B * K];
__device__ float g_factor[B * K];
__device__ float g_acc[4];              // [0]=dist/B [1]=reg/B [2]=var
__device__ unsigned g_ticket;
__device__ unsigned char g_labels[B * L];

// ---------------------------------------------------------------------------
// K0 (k_label): read t once (rows >= nc are all-zero and skipped) ->
// per-pixel labels + t_sum. Pure streaming, 8 px/thread, grid (B, 72).
// ---------------------------------------------------------------------------
constexpr int LBLK = L / (256 * 8);      // 72

__global__ __launch_bounds__(256) void k_label(const float* __restrict__ t,
                                               const int* __restrict__ ncp) {
    __shared__ float pool[8 * K];        // per-warp t_sum partials
    const int tid  = threadIdx.x;
    const int lane = tid & 31, wid = tid >> 5;
    const int b    = blockIdx.x;
    const int nc   = __ldg(&ncp[b]);
    const int l    = (blockIdx.y * 256 + tid) * 8;
    const float* tb = t + (size_t)(b * K) * L + l;

    float ts[K];
#pragma unroll
    for (int c = 0; c < K; c++) ts[c] = 0.f;
    float labf[8] = {0.f, 0.f, 0.f, 0.f, 0.f, 0.f, 0.f, 0.f};

#pragma unroll
    for (int c = 0; c < K; c++) {
        if (c >= nc) break;
        float v[8];
        asm("ld.global.v8.b32 {%0,%1,%2,%3,%4,%5,%6,%7}, [%8];"
            : "=f"(v[0]), "=f"(v[1]), "=f"(v[2]), "=f"(v[3]),
              "=f"(v[4]), "=f"(v[5]), "=f"(v[6]), "=f"(v[7])
            : "l"(tb + (size_t)c * L));
        ts[c] = ((v[0] + v[1]) + (v[2] + v[3])) + ((v[4] + v[5]) + (v[6] + v[7]));
        const float cf = (float)c;
#pragma unroll
        for (int j = 0; j < 8; j++) labf[j] += cf * v[j];
    }

    // pack 8 label bytes -> 2 words, one 8B store (coalesced)
    uint32_t w0 = 0, w1 = 0;
#pragma unroll
    for (int j = 0; j < 4; j++) {
        w0 |= ((uint32_t)(int)(labf[j] + 0.5f)) << (8 * j);
        w1 |= ((uint32_t)(int)(labf[4 + j] + 0.5f)) << (8 * j);
    }
    asm volatile("st.global.v2.b32 [%0], {%1, %2};"
                 :: "l"(g_labels + (size_t)b * L + l), "r"(w0), "r"(w1));

    // t_sum: warp reduce each cluster, then block reduce, then 1 atomic each
#pragma unroll
    for (int c = 0; c < K; c++) {
        if (c >= nc) break;
        float v = ts[c];
#pragma unroll
        for (int off = 16; off; off >>= 1) v += __shfl_down_sync(0xffffffffu, v, off);
        if (lane == 0) pool[wid * K + c] = v;
    }
    __syncthreads();
    if (tid < K && tid < nc) {
        float s = 0.f;
#pragma unroll
        for (int ww = 0; ww < 8; ww++) s += pool[ww * K + tid];
        atomicAdd(&g_tsum[b * K + tid], s);
    }
}

// ---------------------------------------------------------------------------
// K1 (k_sums2): sums[b,f,c] = sum_l x[f,l]*onehot(lab[l]==c).
// Reads ONLY x (evict_last) + labels; reconstructs one-hot tiles in smem
// (set/clear one cell per pixel — Ts stays zero elsewhere).
// Compute map: h = tid>>7 (12-cluster half), g = (tid&127)>>4 (16 px),
// fi = tid&15 (feature). f32x2 FFMA, early break at nc4.
// ---------------------------------------------------------------------------
constexpr int TP  = 128;
constexpr int TPB = 8;
constexpr int NCHUNK = L / (TP * TPB);   // 144
constexpr int XST = 132;                 // padded row stride (floats)

__global__ __launch_bounds__(256, 3) void k_sums(const float* __restrict__ x,
                                                 const int* __restrict__ ncp) {
    __shared__ __align__(16) float xs[2][F * XST];      // 16.9 KB
    __shared__ __align__(16) float Ts[K * XST];         // 12.7 KB one-hot
    __shared__ __align__(16) unsigned char labs[2][TP];

    const int tid  = threadIdx.x;
    const int lane = tid & 31;
    const int w    = tid >> 5;
    const int b    = blockIdx.x;
    const int h    = tid >> 7;
    const int rem  = tid & 127;
    const int g    = rem >> 4;
    const int fi   = rem & 15;
    const int nc   = __ldg(&ncp[b]);
    const int nc4  = (nc + 3) & ~3;
    const int cnt  = min(max(nc4 - h * 12, 0), 12);
    const float* xb = x + (size_t)(b * F) * L;
    const int l0b = blockIdx.y * (TP * TPB);

    // zero the one-hot tile once
    for (int i = tid; i < K * XST / 4; i += 256)
        *(float4*)(Ts + i * 4) = make_float4(0.f, 0.f, 0.f, 0.f);

    uint32_t sx[2], sl[2];
    sx[0] = (uint32_t)__cvta_generic_to_shared(&xs[0][0]);
    sx[1] = (uint32_t)__cvta_generic_to_shared(&xs[1][0]);
    sl[0] = (uint32_t)__cvta_generic_to_shared(&labs[0][0]);
    sl[1] = (uint32_t)__cvta_generic_to_shared(&labs[1][0]);

    uint64_t pol;   // keep x resident in L2 for k_var
    asm("createpolicy.fractional.L2::evict_last.b64 %0, 1.0;" : "=l"(pol));

    unsigned long long acc[12];
#pragma unroll
    for (int j = 0; j < 12; j++) acc[j] = 0ull;

    const int xr0 = 2 * w, xr1 = 2 * w + 1;   // warp w loads x rows 2w, 2w+1

#define CPX(DST, SRC) \
    asm volatile("cp.async.cg.shared.global.L2::cache_hint [%0], [%1], 16, %2;" \
                 :: "r"(DST), "l"(SRC), "l"(pol))
#define CPL(DST, SRC) \
    asm volatile("cp.async.cg.shared.global [%0], [%1], 16;" :: "r"(DST), "l"(SRC))

#define ISSUE(TILE, BI)                                                        \
    {                                                                          \
        const int l0_ = l0b + (TILE) * TP;                                     \
        CPX(sx[BI] + (uint32_t)((xr0 * XST + lane * 4) * 4),                   \
            xb + (size_t)xr0 * L + l0_ + lane * 4);                            \
        CPX(sx[BI] + (uint32_t)((xr1 * XST + lane * 4) * 4),                   \
            xb + (size_t)xr1 * L + l0_ + lane * 4);                            \
        if (tid < 8) CPL(sl[BI] + (uint32_t)(tid * 16),                        \
                         g_labels + (size_t)b * L + l0_ + tid * 16);           \
        asm volatile("cp.async.commit_group;");                                \
    }

    ISSUE(0, 0);
    int prevlab = -1;
    __syncthreads();                      // Ts zero visible

#pragma unroll 1
    for (int tile = 0; tile < TPB; ++tile) {
        const int cur = tile & 1;
        if (tile + 1 < TPB) {
            ISSUE(tile + 1, cur ^ 1);
            asm volatile("cp.async.wait_group 1;");
        } else {
            asm volatile("cp.async.wait_group 0;");
        }
        __syncthreads();                  // data ready; prev GEMM done

        // thread p<128 owns column p of Ts: clear old cell, set new one
        if (tid < TP) {
            if (prevlab >= 0) Ts[prevlab * XST + tid] = 0.f;
            const int lab = (int)labs[cur][tid];
            Ts[lab * XST + tid] = 1.0f;
            prevlab = lab;
        }
        __syncthreads();                  // one-hot visible

        // ---- GEMM: 16 contiguous px, 12 clusters, f32x2 FFMA ----
        {
            const float* Xp = &xs[cur][0] + fi * XST + g * 16;
            const ulonglong2 xa = *(const ulonglong2*)(Xp);
            const ulonglong2 xv = *(const ulonglong2*)(Xp + 4);
            const ulonglong2 xc = *(const ulonglong2*)(Xp + 8);
            const ulonglong2 xd = *(const ulonglong2*)(Xp + 12);
#pragma unroll
            for (int j = 0; j < 12; j++) {
                if ((j & 3) == 0 && j >= cnt) break;      // uniform per warp
                const float* Tp = Ts + (h * 12 + j) * XST + g * 16;
                const ulonglong2 ta = *(const ulonglong2*)(Tp);
                const ulonglong2 tv = *(const ulonglong2*)(Tp + 4);
                const ulonglong2 tc = *(const ulonglong2*)(Tp + 8);
                const ulonglong2 td = *(const ulonglong2*)(Tp + 12);
                asm("fma.rn.f32x2 %0, %1, %2, %0;" : "+l"(acc[j]) : "l"(xa.x), "l"(ta.x));
                asm("fma.rn.f32x2 %0, %1, %2, %0;" : "+l"(acc[j]) : "l"(xa.y), "l"(ta.y));
                asm("fma.rn.f32x2 %0, %1, %2, %0;" : "+l"(acc[j]) : "l"(xv.x), "l"(tv.x));
                asm("fma.rn.f32x2 %0, %1, %2, %0;" : "+l"(acc[j]) : "l"(xv.y), "l"(tv.y));
                asm("fma.rn.f32x2 %0, %1, %2, %0;" : "+l"(acc[j]) : "l"(xc.x), "l"(tc.x));
                asm("fma.rn.f32x2 %0, %1, %2, %0;" : "+l"(acc[j]) : "l"(xc.y), "l"(tc.y));
                asm("fma.rn.f32x2 %0, %1, %2, %0;" : "+l"(acc[j]) : "l"(xd.x), "l"(td.x));
                asm("fma.rn.f32x2 %0, %1, %2, %0;" : "+l"(acc[j]) : "l"(xd.y), "l"(td.y));
            }
        }
        __syncthreads();                  // done reading xs[cur] / Ts
    }
#undef ISSUE
#undef CPX
#undef CPL

    // ---- block reduction: 8 group-partials per (f,c) ----
    float* pool = &xs[0][0];             // 256*12 = 3072 floats, fits
#pragma unroll
    for (int j = 0; j < 12; j++) {
        const float lo = __uint_as_float((uint32_t)(acc[j] & 0xffffffffull));
        const float hi = __uint_as_float((uint32_t)(acc[j] >> 32));
        pool[tid * 12 + j] = lo + hi;
    }
    __syncthreads();
    for (int i = tid; i < F * K; i += 256) {
        const int f = i / K, c = i % K;
        if (c < nc) {
            const int hh = c / 12, jj = c % 12;
            float s = 0.f;
#pragma unroll
            for (int gg = 0; gg < 8; gg++)
                s += pool[(hh * 128 + gg * 16 + f) * 12 + jj];
            atomicAdd(&g_sums[(b * F + f) * K + c], s);
        }
    }
}

// ---------------------------------------------------------------------------
// K2: means, m2, variance factor, pairwise-distance + reg terms.
// ---------------------------------------------------------------------------
__global__ void k_means(const int* __restrict__ n_clusters) {
    __shared__ float ms[F * K];
    __shared__ float m2s[K];
    __shared__ float red[32];

    const int b   = blockIdx.x;
    const int tid = threadIdx.x;
    const int nc  = n_clusters[b];
    const float ncf = (float)nc;

    if (tid < F * K) {
        const int c = tid % K;
        float m = g_sums[b * F * K + tid] / (g_tsum[b * K + c] + EPSV);
        m = (c < nc) ? m : 0.f;
        ms[tid] = m;
        g_means[b * F * K + tid] = m;
    }
    __syncthreads();
    if (tid < K) {
        float m2 = 0.f;
#pragma unroll
        for (int f = 0; f < F; f++) { const float v = ms[f * K + tid]; m2 += v * v; }
        m2s[tid] = m2;
        g_m2[b * K + tid] = m2;
        const float ts = g_tsum[b * K + tid];
        g_factor[b * K + tid] = (tid < nc)
            ? (1.f / (ts + EPSV)) * (1.f / (ncf + EPSV)) * (1.f / (float)B) : 0.f;
    }
    __syncthreads();

    float regp = 0.f;
    if (tid < K && tid < nc) {
        const float m2 = m2s[tid];
        regp = (m2 > 0.f) ? sqrtf(m2) : 0.f;
    }
    float hs = 0.f;
    {
        const int cc = tid / K, dd = tid % K;
        if (cc != dd && cc < nc && dd < nc) {
            float mm = 0.f;
#pragma unroll
            for (int f = 0; f < F; f++) mm += ms[f * K + cc] * ms[f * K + dd];
            float pd2 = fmaxf(m2s[cc] - 2.f * mm + m2s[dd], 0.f);
            const float pdist = (pd2 > 0.f) ? sqrtf(pd2) : 0.f;
            const float h = fmaxf(2.f * DELTA_DIST - pdist, 0.f);
            hs = h * h;
        }
    }
    const int lane = tid & 31, wid = tid >> 5;   // 18 warps
#pragma unroll
    for (int off = 16; off; off >>= 1) hs += __shfl_down_sync(0xffffffffu, hs, off);
    if (lane == 0) red[wid] = hs;
    __syncthreads();
    float hs_tot = 0.f;
    if (tid < 32) {
        float v = (tid < 18) ? red[tid] : 0.f;
#pragma unroll
        for (int off = 16; off; off >>= 1) v += __shfl_down_sync(0xffffffffu, v, off);
        hs_tot = v;
    }
    __syncthreads();
#pragma unroll
    for (int off = 16; off; off >>= 1) regp += __shfl_down_sync(0xffffffffu, regp, off);
    if (lane == 0) red[wid] = regp;
    __syncthreads();
    if (tid == 0) {
        float reg_tot = 0.f;
        for (int i = 0; i < 18; i++) reg_tot += red[i];
        const float dist_per = hs_tot / (2.f * ncf * (ncf - 1.f) + EPSV);
        if (nc > 1) atomicAdd(&g_acc[0], dist_per / (float)B);
        if (nc > 0) atomicAdd(&g_acc[1], reg_tot / ncf / (float)B);
    }
}

// ---------------------------------------------------------------------------
// K3: variance term. 8 px/thread via 256-bit loads (x should be L2-warm);
// block reduce -> 1 atomic. Last block writes out + re-zeroes scratch.
// ---------------------------------------------------------------------------
constexpr int VBLK = L / (256 * 8);      // 72

__global__ __launch_bounds__(256) void k_var(const float* __restrict__ x,
                                             float* __restrict__ out) {
    __shared__ float ms[F * K];
    __shared__ float m2s[K];
    __shared__ float fac[K];
    __shared__ float red[8];
    __shared__ int amLast;

    const int b   = blockIdx.x;
    const int tid = threadIdx.x;
    for (int i = tid; i < F * K; i += 256) ms[i] = g_means[b * F * K + i];
    if (tid < K) { m2s[tid] = g_m2[b * K + tid]; fac[tid] = g_factor[b * K + tid]; }
    __syncthreads();

    const int l = (blockIdx.y * 256 + tid) * 8;
    const uint2 lw = __ldg((const uint2*)(g_labels + (size_t)b * L + l));
    int lab[8];
    lab[0] = (int)(lw.x & 255);  lab[1] = (int)((lw.x >> 8) & 255);
    lab[2] = (int)((lw.x >> 16) & 255);  lab[3] = (int)((lw.x >> 24) & 255);
    lab[4] = (int)(lw.y & 255);  lab[5] = (int)((lw.y >> 8) & 255);
    lab[6] = (int)((lw.y >> 16) & 255);  lab[7] = (int)((lw.y >> 24) & 255);

    float x2[8], xm[8];
#pragma unroll
    for (int j = 0; j < 8; j++) { x2[j] = 0.f; xm[j] = 0.f; }

    const float* xb = x + (size_t)(b * F) * L + l;
#pragma unroll
    for (int f = 0; f < F; f++) {
        float v[8];
        asm("ld.global.v8.b32 {%0,%1,%2,%3,%4,%5,%6,%7}, [%8];"
            : "=f"(v[0]), "=f"(v[1]), "=f"(v[2]), "=f"(v[3]),
              "=f"(v[4]), "=f"(v[5]), "=f"(v[6]), "=f"(v[7])
            : "l"(xb + (size_t)f * L));
        const float* msf = ms + f * K;
#pragma unroll
        for (int j = 0; j < 8; j++) {
            x2[j] += v[j] * v[j];
            xm[j] += v[j] * msf[lab[j]];
        }
    }
    float a = 0.f;
#pragma unroll
    for (int j = 0; j < 8; j++) {
        const float d2 = fmaxf(x2[j] - 2.f * xm[j] + m2s[lab[j]], 0.f);
        const float h = ((d2 > 0.f) ? sqrtf(d2) : 0.f) - DELTA_VAR;
        if (h > 0.f) a += h * h * fac[lab[j]];
    }
    const int lane = tid & 31, wid = tid >> 5;
#pragma unroll
    for (int off = 16; off; off >>= 1) a += __shfl_down_sync(0xffffffffu, a, off);
    if (lane == 0) red[wid] = a;
    __syncthreads();
    if (tid == 0) {
        float s = 0.f;
#pragma unroll
        for (int i = 0; i < 8; i++) s += red[i];
        atomicAdd(&g_acc[2], s);
        __threadfence();
        const unsigned tk = atomicAdd(&g_ticket, 1u);
        amLast = (tk == (unsigned)(VBLK * B) - 1u) ? 1 : 0;
    }
    __syncthreads();
    if (amLast) {
        if (tid == 0) {
            volatile float* ga = g_acc;
            out[0] = ga[2] + ga[0] + GAMMA * ga[1];
            g_acc[0] = 0.f; g_acc[1] = 0.f; g_acc[2] = 0.f; g_acc[3] = 0.f;
            g_ticket = 0u;
        }
        for (int i = tid; i < B * F * K; i += 256) g_sums[i] = 0.f;
        for (int i = tid; i < B * K; i += 256) g_tsum[i] = 0.f;
    }
}

// ---------------------------------------------------------------------------
extern "C" void kernel_launch(void* const* d_in, const int* in_sizes, int n_in,
                              void* d_out, int out_size) {
    const float* x  = (const float*)d_in[0];
    const float* t  = (const float*)d_in[1];
    const int*   nc = (const int*)d_in[2];
    float* out = (float*)d_out;

    k_label<<<dim3(B, LBLK), 256>>>(t, nc);
    k_sums<<<dim3(B, NCHUNK), 256>>>(x, nc);
    k_means<<<B, 576>>>(nc);
    k_var<<<dim3(B, VBLK), 256>>>(x, out);
}

// round 11
// speedup vs baseline: 1.2627x; 1.2627x over previous
#include <cuda_runtime.h>
#include <cstdint>

constexpr int   B = 8, F = 16, K = 24;
constexpr int   L = 384 * 384;          // 147456 pixels per (b, plane)
constexpr float EPSV       = 1e-8f;
constexpr float DELTA_VAR  = 0.5f;
constexpr float DELTA_DIST = 1.5f;
constexpr float GAMMA      = 0.001f;

// Scratch (device globals; statically zero-initialized for the first call,
// re-zeroed by the last k_var block for subsequent graph replays)
__device__ float g_sums[B * F * K];
__device__ float g_tsum[B * K];
__device__ float g_means[B * F * K];
__device__ float g_m2[B * K];
__device__ float g_factor[B * K];
__device__ float g_acc[4];              // [0]=dist/B [1]=reg/B [2]=var
__device__ unsigned g_ticket;
__device__ unsigned char g_labels[B * L];

// ---------------------------------------------------------------------------
// K1: sums[b,f,c], t_sum[b,c], labels — fused t+x pass, 3-stage cp.async,
// ONE __syncthreads per tile. t rows >= nc skipped (all-zero).
// Compute map: h = tid>>7 (12-cluster half), g = (tid&127)>>4 (16 px),
// fi = tid&15 (feature). Packed f32x2 FFMA, early break at nc4.
// ---------------------------------------------------------------------------
constexpr int TP  = 128;
constexpr int TPB = 8;
constexpr int NCHUNK = L / (TP * TPB);   // 144
constexpr int XST = 132;                 // padded row stride (floats)
constexpr int TS_OFF = F * XST;
constexpr int BUF_FLOATS = (F + K) * XST;        // 5280
constexpr int SMEM_BYTES = 3 * BUF_FLOATS * 4;   // 63360

__global__ __launch_bounds__(256, 3) void k_sums(const float* __restrict__ x,
                                                 const float* __restrict__ t,
                                                 const int* __restrict__ ncp) {
    extern __shared__ __align__(16) float sm[];   // 3 stages

    const int tid  = threadIdx.x;
    const int w    = tid >> 5;
    const int lane = tid & 31;
    const int b    = blockIdx.y;
    const int h    = tid >> 7;           // cluster half (12 c each)
    const int rem  = tid & 127;
    const int g    = rem >> 4;           // pixel group 0..7 (16 px)
    const int fi   = rem & 15;           // feature row
    const int nc   = __ldg(&ncp[b]);
    const int nc4  = (nc + 3) & ~3;
    const int cnt  = min(max(nc4 - h * 12, 0), 12);   // uniform per warp
    const float* xb = x + (size_t)(b * F) * L;
    const float* tb = t + (size_t)(b * K) * L;
    const int l0b = blockIdx.x * (TP * TPB);

    uint32_t sb[3];
    sb[0] = (uint32_t)__cvta_generic_to_shared(sm);
    sb[1] = sb[0] + (uint32_t)(BUF_FLOATS * 4);
    sb[2] = sb[1] + (uint32_t)(BUF_FLOATS * 4);

    uint64_t polX, polT;
    asm("createpolicy.fractional.L2::evict_last.b64 %0, 1.0;"  : "=l"(polX));
    asm("createpolicy.fractional.L2::evict_first.b64 %0, 1.0;" : "=l"(polT));

    unsigned long long acc[12];
#pragma unroll
    for (int j = 0; j < 12; j++) acc[j] = 0ull;
    float ts[6] = {0.f, 0.f, 0.f, 0.f, 0.f, 0.f};
    const int u = w - 4;                 // t_sum warp index (valid for w>=4)

    const int xr0 = 2 * w, xr1 = 2 * w + 1;        // warp w loads x rows 2w,2w+1
    const int tc0 = 3 * w, tc1 = 3 * w + 1, tc2 = 3 * w + 2;

#define CPH(DST, SRC, POL)                                                     \
    asm volatile("cp.async.cg.shared.global.L2::cache_hint [%0], [%1], 16, %2;" \
                 :: "r"(DST), "l"(SRC), "l"(POL))

#define ISSUE(TILE)                                                            \
    {                                                                          \
        const int l0_ = l0b + (TILE) * TP;                                     \
        const uint32_t s_ = sb[(TILE) % 3];                                    \
        CPH(s_ + (uint32_t)((xr0 * XST + lane * 4) * 4),                       \
            xb + (size_t)xr0 * L + l0_ + lane * 4, polX);                      \
        CPH(s_ + (uint32_t)((xr1 * XST + lane * 4) * 4),                       \
            xb + (size_t)xr1 * L + l0_ + lane * 4, polX);                      \
        if (tc0 < nc) CPH(s_ + (uint32_t)((TS_OFF + tc0 * XST + lane * 4) * 4), \
                          tb + (size_t)tc0 * L + l0_ + lane * 4, polT);        \
        if (tc1 < nc) CPH(s_ + (uint32_t)((TS_OFF + tc1 * XST + lane * 4) * 4), \
                          tb + (size_t)tc1 * L + l0_ + lane * 4, polT);        \
        if (tc2 < nc) CPH(s_ + (uint32_t)((TS_OFF + tc2 * XST + lane * 4) * 4), \
                          tb + (size_t)tc2 * L + l0_ + lane * 4, polT);        \
        asm volatile("cp.async.commit_group;");                                \
    }

    ISSUE(0);
    ISSUE(1);

#pragma unroll 1
    for (int tile = 0; tile < TPB; ++tile) {
        // tile's data must be complete: allow 1 pending (tile+1) mid-stream
        if (tile + 1 < TPB) { asm volatile("cp.async.wait_group 1;"); }
        else                { asm volatile("cp.async.wait_group 0;"); }
        __syncthreads();     // data visible; prev tile's readers all done

        // issue tile+2 into buffer (tile+2)%3 — its readers finished at
        // tile-1, which the sync above ordered before us.
        if (tile + 2 < TPB) ISSUE(tile + 2);

        const float* bc = sm + (tile % 3) * BUF_FLOATS;
        const int l0 = l0b + tile * TP;

        // ---- aux: lower 128 threads -> labels; upper 4 warps -> t_sum ----
        if (tid < TP) {
            const float* Tp = bc + TS_OFF + tid;
            float labf = 0.f, cf = 0.f;
            for (int c = 0; c < nc; c++) { labf += cf * Tp[c * XST]; cf += 1.f; }
            g_labels[(size_t)b * L + l0 + tid] = (unsigned char)(int)(labf + 0.5f);
        } else {
#pragma unroll
            for (int i = 0; i < 6; i++) {
                const int c = u * 6 + i;
                if (c < nc) {
                    const float4 v = *(const float4*)(bc + TS_OFF + c * XST + lane * 4);
                    ts[i] += (v.x + v.y) + (v.z + v.w);
                }
            }
        }

        // ---- GEMM: 16 contiguous px, 12 clusters, f32x2 FFMA ----
        {
            const float* Xp = bc + fi * XST + g * 16;
            const ulonglong2 xa = *(const ulonglong2*)(Xp);
            const ulonglong2 xv = *(const ulonglong2*)(Xp + 4);
            const ulonglong2 xc = *(const ulonglong2*)(Xp + 8);
            const ulonglong2 xd = *(const ulonglong2*)(Xp + 12);
#pragma unroll
            for (int j = 0; j < 12; j++) {
                if ((j & 3) == 0 && j >= cnt) break;       // uniform per warp
                const float* Tp = bc + TS_OFF + (h * 12 + j) * XST + g * 16;
                const ulonglong2 ta = *(const ulonglong2*)(Tp);
                const ulonglong2 tv = *(const ulonglong2*)(Tp + 4);
                const ulonglong2 tc = *(const ulonglong2*)(Tp + 8);
                const ulonglong2 td = *(const ulonglong2*)(Tp + 12);
                asm("fma.rn.f32x2 %0, %1, %2, %0;" : "+l"(acc[j]) : "l"(xa.x), "l"(ta.x));
                asm("fma.rn.f32x2 %0, %1, %2, %0;" : "+l"(acc[j]) : "l"(xa.y), "l"(ta.y));
                asm("fma.rn.f32x2 %0, %1, %2, %0;" : "+l"(acc[j]) : "l"(xv.x), "l"(tv.x));
                asm("fma.rn.f32x2 %0, %1, %2, %0;" : "+l"(acc[j]) : "l"(xv.y), "l"(tv.y));
                asm("fma.rn.f32x2 %0, %1, %2, %0;" : "+l"(acc[j]) : "l"(xc.x), "l"(tc.x));
                asm("fma.rn.f32x2 %0, %1, %2, %0;" : "+l"(acc[j]) : "l"(xc.y), "l"(tc.y));
                asm("fma.rn.f32x2 %0, %1, %2, %0;" : "+l"(acc[j]) : "l"(xd.x), "l"(td.x));
                asm("fma.rn.f32x2 %0, %1, %2, %0;" : "+l"(acc[j]) : "l"(xd.y), "l"(td.y));
            }
        }
        // no end-of-tile sync: next iteration's top sync protects reuse
    }
#undef ISSUE
#undef CPH

    __syncthreads();
    // ---- block reduction: 8 group-partials per (f,c) ----
    float* pool = sm;                    // 256*12 = 3072 floats, fits stage 0
#pragma unroll
    for (int j = 0; j < 12; j++) {
        const float lo = __uint_as_float((uint32_t)(acc[j] & 0xffffffffull));
        const float hi = __uint_as_float((uint32_t)(acc[j] >> 32));
        pool[tid * 12 + j] = lo + hi;
    }
    __syncthreads();
    for (int i = tid; i < F * K; i += 256) {
        const int f = i / K, c = i % K;
        if (c < nc) {
            const int hh = c / 12, jj = c % 12;
            float s = 0.f;
#pragma unroll
            for (int gg = 0; gg < 8; gg++)
                s += pool[(hh * 128 + gg * 16 + f) * 12 + jj];
            atomicAdd(&g_sums[(b * F + f) * K + c], s);
        }
    }
    if (w >= 4) {
#pragma unroll
        for (int i = 0; i < 6; i++) {
            const int c = u * 6 + i;
            float v = ts[i];
#pragma unroll
            for (int off = 16; off; off >>= 1)
                v += __shfl_down_sync(0xffffffffu, v, off);
            if (lane == 0 && c < nc) atomicAdd(&g_tsum[b * K + c], v);
        }
    }
}

// ---------------------------------------------------------------------------
// K2: means, m2, variance factor, pairwise-distance + reg terms.
// ---------------------------------------------------------------------------
__global__ void k_means(const int* __restrict__ n_clusters) {
    __shared__ float ms[F * K];
    __shared__ float m2s[K];
    __shared__ float red[32];

    const int b   = blockIdx.x;
    const int tid = threadIdx.x;
    const int nc  = n_clusters[b];
    const float ncf = (float)nc;

    if (tid < F * K) {
        const int c = tid % K;
        float m = g_sums[b * F * K + tid] / (g_tsum[b * K + c] + EPSV);
        m = (c < nc) ? m : 0.f;
        ms[tid] = m;
        g_means[b * F * K + tid] = m;
    }
    __syncthreads();
    if (tid < K) {
        float m2 = 0.f;
#pragma unroll
        for (int f = 0; f < F; f++) { const float v = ms[f * K + tid]; m2 += v * v; }
        m2s[tid] = m2;
        g_m2[b * K + tid] = m2;
        const float ts = g_tsum[b * K + tid];
        g_factor[b * K + tid] = (tid < nc)
            ? (1.f / (ts + EPSV)) * (1.f / (ncf + EPSV)) * (1.f / (float)B) : 0.f;
    }
    __syncthreads();

    float regp = 0.f;
    if (tid < K && tid < nc) {
        const float m2 = m2s[tid];
        regp = (m2 > 0.f) ? sqrtf(m2) : 0.f;
    }
    float hs = 0.f;
    {
        const int cc = tid / K, dd = tid % K;
        if (cc != dd && cc < nc && dd < nc) {
            float mm = 0.f;
#pragma unroll
            for (int f = 0; f < F; f++) mm += ms[f * K + cc] * ms[f * K + dd];
            float pd2 = fmaxf(m2s[cc] - 2.f * mm + m2s[dd], 0.f);
            const float pdist = (pd2 > 0.f) ? sqrtf(pd2) : 0.f;
            const float h = fmaxf(2.f * DELTA_DIST - pdist, 0.f);
            hs = h * h;
        }
    }
    const int lane = tid & 31, wid = tid >> 5;   // 18 warps
#pragma unroll
    for (int off = 16; off; off >>= 1) hs += __shfl_down_sync(0xffffffffu, hs, off);
    if (lane == 0) red[wid] = hs;
    __syncthreads();
    float hs_tot = 0.f;
    if (tid < 32) {
        float v = (tid < 18) ? red[tid] : 0.f;
#pragma unroll
        for (int off = 16; off; off >>= 1) v += __shfl_down_sync(0xffffffffu, v, off);
        hs_tot = v;
    }
    __syncthreads();
#pragma unroll
    for (int off = 16; off; off >>= 1) regp += __shfl_down_sync(0xffffffffu, regp, off);
    if (lane == 0) red[wid] = regp;
    __syncthreads();
    if (tid == 0) {
        float reg_tot = 0.f;
        for (int i = 0; i < 18; i++) reg_tot += red[i];
        const float dist_per = hs_tot / (2.f * ncf * (ncf - 1.f) + EPSV);
        if (nc > 1) atomicAdd(&g_acc[0], dist_per / (float)B);
        if (nc > 0) atomicAdd(&g_acc[1], reg_tot / ncf / (float)B);
    }
}

// ---------------------------------------------------------------------------
// K3: variance term. 8 px/thread via 256-bit loads (x L2-warm from k_sums'
// evict_last); block reduce -> 1 atomic. Last block writes out + re-zeroes.
// grid (VBLK, B): chunk-fastest ordering (measured faster than b-fastest).
// ---------------------------------------------------------------------------
constexpr int VBLK = L / (256 * 8);      // 72

__global__ __launch_bounds__(256) void k_var(const float* __restrict__ x,
                                             float* __restrict__ out) {
    __shared__ float ms[F * K];
    __shared__ float m2s[K];
    __shared__ float fac[K];
    __shared__ float red[8];
    __shared__ int amLast;

    const int b   = blockIdx.y;
    const int tid = threadIdx.x;
    for (int i = tid; i < F * K; i += 256) ms[i] = g_means[b * F * K + i];
    if (tid < K) { m2s[tid] = g_m2[b * K + tid]; fac[tid] = g_factor[b * K + tid]; }
    __syncthreads();

    const int l = (blockIdx.x * 256 + tid) * 8;
    const uint2 lw = __ldg((const uint2*)(g_labels + (size_t)b * L + l));
    int lab[8];
    lab[0] = (int)(lw.x & 255);  lab[1] = (int)((lw.x >> 8) & 255);
    lab[2] = (int)((lw.x >> 16) & 255);  lab[3] = (int)((lw.x >> 24) & 255);
    lab[4] = (int)(lw.y & 255);  lab[5] = (int)((lw.y >> 8) & 255);
    lab[6] = (int)((lw.y >> 16) & 255);  lab[7] = (int)((lw.y >> 24) & 255);

    float x2[8], xm[8];
#pragma unroll
    for (int j = 0; j < 8; j++) { x2[j] = 0.f; xm[j] = 0.f; }

    const float* xb = x + (size_t)(b * F) * L + l;
#pragma unroll
    for (int f = 0; f < F; f++) {
        float v[8];
        asm("ld.global.v8.b32 {%0,%1,%2,%3,%4,%5,%6,%7}, [%8];"
            : "=f"(v[0]), "=f"(v[1]), "=f"(v[2]), "=f"(v[3]),
              "=f"(v[4]), "=f"(v[5]), "=f"(v[6]), "=f"(v[7])
            : "l"(xb + (size_t)f * L));
        const float* msf = ms + f * K;
#pragma unroll
        for (int j = 0; j < 8; j++) {
            x2[j] += v[j] * v[j];
            xm[j] += v[j] * msf[lab[j]];
        }
    }
    float a = 0.f;
#pragma unroll
    for (int j = 0; j < 8; j++) {
        const float d2 = fmaxf(x2[j] - 2.f * xm[j] + m2s[lab[j]], 0.f);
        const float h = ((d2 > 0.f) ? sqrtf(d2) : 0.f) - DELTA_VAR;
        if (h > 0.f) a += h * h * fac[lab[j]];
    }
    const int lane = tid & 31, wid = tid >> 5;
#pragma unroll
    for (int off = 16; off; off >>= 1) a += __shfl_down_sync(0xffffffffu, a, off);
    if (lane == 0) red[wid] = a;
    __syncthreads();
    if (tid == 0) {
        float s = 0.f;
#pragma unroll
        for (int i = 0; i < 8; i++) s += red[i];
        atomicAdd(&g_acc[2], s);
        __threadfence();
        const unsigned tk = atomicAdd(&g_ticket, 1u);
        amLast = (tk == (unsigned)(VBLK * B) - 1u) ? 1 : 0;
    }
    __syncthreads();
    if (amLast) {
        if (tid == 0) {
            volatile float* ga = g_acc;
            out[0] = ga[2] + ga[0] + GAMMA * ga[1];
            g_acc[0] = 0.f; g_acc[1] = 0.f; g_acc[2] = 0.f; g_acc[3] = 0.f;
            g_ticket = 0u;
        }
        for (int i = tid; i < B * F * K; i += 256) g_sums[i] = 0.f;
        for (int i = tid; i < B * K; i += 256) g_tsum[i] = 0.f;
    }
}

// ---------------------------------------------------------------------------
extern "C" void kernel_launch(void* const* d_in, const int* in_sizes, int n_in,
                              void* d_out, int out_size) {
    const float* x  = (const float*)d_in[0];
    const float* t  = (const float*)d_in[1];
    const int*   nc = (const int*)d_in[2];
    float* out = (float*)d_out;

    static int smem_set = 0;
    if (!smem_set) {
        cudaFuncSetAttribute(k_sums, cudaFuncAttributeMaxDynamicSharedMemorySize,
                             SMEM_BYTES);
        smem_set = 1;
    }

    k_sums<<<dim3(NCHUNK, B), 256, SMEM_BYTES>>>(x, t, nc);
    k_means<<<B, 576>>>(nc);
    k_var<<<dim3(VBLK, B), 256>>>(x, out);
}